// round 11
// baseline (speedup 1.0000x reference)
#include <cuda_runtime.h>
#include <cuda_bf16.h>
#include <cstdint>

// ---------------- problem constants ----------------
#define NGRAPH 8192
#define NPG    39
#define EPG    312
#define NTOT   (NGRAPH * NPG)
#define ETOT   (NGRAPH * EPG)
#define FDIM   4560
#define KP     4608            // FDIM padded to 64
#define NEG_SLOPE 0.2f

#define OFF_RES0 0
#define OFF_RES1 39
#define OFF_RES2 351
#define OFF_RES3 2847
#define OFF_RES4 4095
#define OFF_OUT0 4446
#define OFF_OUT1 4447
#define OFF_OUT2 4455
#define OFF_OUT3 4519
#define OFF_OUT4 4551

// ---------------- scratch (device globals) ----------------
__device__ __nv_bfloat16 g_Ahi[(size_t)NGRAPH * KP];   // 75.5 MB
__device__ __nv_bfloat16 g_Alo[(size_t)NGRAPH * KP];   // 75.5 MB
__device__ __nv_bfloat16 g_Bhi[(size_t)1024 * KP];     // 9.4 MB
__device__ __nv_bfloat16 g_Blo[(size_t)1024 * KP];     // 9.4 MB
__device__ float g_m1[(size_t)NGRAPH * 1024];          // 33.5 MB
__device__ float g_m2[(size_t)NGRAPH * 128];           // 4.2 MB

// ---------------- generic helpers ----------------
__device__ __forceinline__ float lrelu(float v) { return v >= 0.f ? v : NEG_SLOPE * v; }
__device__ __forceinline__ void store_hl(__nv_bfloat16* hi, __nv_bfloat16* lo,
                                         int idx, float v) {
    __nv_bfloat16 h = __float2bfloat16(v);
    hi[idx] = h;
    lo[idx] = __float2bfloat16(v - __bfloat162float(h));
}
__device__ __forceinline__ uint32_t smem_u32(const void* p) {
    uint32_t a;
    asm("{ .reg .u64 t; cvta.to.shared.u64 t, %1; cvt.u32.u64 %0, t; }" : "=r"(a) : "l"(p));
    return a;
}

// f32x2 packed FMA helpers
__device__ __forceinline__ unsigned long long pk2(float x, float y) {
    unsigned long long u;
    asm("mov.b64 %0, {%1, %2};" : "=l"(u) : "f"(x), "f"(y));
    return u;
}
__device__ __forceinline__ void upk2(unsigned long long u, float& x, float& y) {
    asm("mov.b64 {%0, %1}, %2;" : "=f"(x), "=f"(y) : "l"(u));
}
__device__ __forceinline__ void ffma2(unsigned long long& c, unsigned long long a,
                                      unsigned long long b) {
    asm("fma.rn.f32x2 %0, %1, %2, %0;" : "+l"(c) : "l"(a), "l"(b));
}

// ---------------- cp.async / ldmatrix / mma helpers ----------------
__device__ __forceinline__ void cp_async16(uint32_t dst, const void* src) {
    asm volatile("cp.async.cg.shared.global [%0], [%1], 16;" :: "r"(dst), "l"(src));
}
__device__ __forceinline__ void cp_commit() {
    asm volatile("cp.async.commit_group;" ::: "memory");
}
template <int N>
__device__ __forceinline__ void cp_wait_group() {
    asm volatile("cp.async.wait_group %0;" :: "n"(N) : "memory");
}
__device__ __forceinline__ void ldsm_x4(uint32_t* r, uint32_t addr) {
    asm volatile("ldmatrix.sync.aligned.m8n8.x4.shared.b16 {%0,%1,%2,%3}, [%4];"
                 : "=r"(r[0]), "=r"(r[1]), "=r"(r[2]), "=r"(r[3]) : "r"(addr));
}
__device__ __forceinline__ void mma16816(float* c, const uint32_t* a, const uint32_t* b) {
    asm volatile(
        "mma.sync.aligned.m16n8k16.row.col.f32.bf16.bf16.f32 "
        "{%0,%1,%2,%3}, {%4,%5,%6,%7}, {%8,%9}, {%0,%1,%2,%3};"
        : "+f"(c[0]), "+f"(c[1]), "+f"(c[2]), "+f"(c[3])
        : "r"(a[0]), "r"(a[1]), "r"(a[2]), "r"(a[3]), "r"(b[0]), "r"(b[1]));
}

// ================= GAT kernel: one CTA per graph, CSR aggregation ==========
template <int Fi, int Fo, int VEC>
__device__ void gat_layer_csr(
    float* __restrict__ xin, float* __restrict__ h, float* __restrict__ Wsh,
    float* __restrict__ sas, float* __restrict__ sad, float* __restrict__ sbi,
    float* __restrict__ ss, float* __restrict__ sd,
    const int* __restrict__ start, const short* __restrict__ elist,
    const float* __restrict__ W, const float* __restrict__ a_s,
    const float* __restrict__ a_d, const float* __restrict__ bias,
    __nv_bfloat16* __restrict__ fhi, __nv_bfloat16* __restrict__ flo,
    int res_off, int pool_off)
{
    const int tid = threadIdx.x;
    for (int i = tid; i < Fi * Fo; i += 256) Wsh[i] = W[i];
    if (tid < Fo) { sas[tid] = a_s[tid]; sad[tid] = a_d[tid]; sbi[tid] = bias[tid]; }
    __syncthreads();

    constexpr int FC = Fo / VEC;
    // h = x @ W (vectorized over output features)
    for (int u = tid; u < NPG * FC; u += 256) {
        int n = u / FC, c = u % FC;
        if constexpr (VEC == 4) {
            const float4* W4 = (const float4*)Wsh;
            float4 acc = {0.f, 0.f, 0.f, 0.f};
            #pragma unroll
            for (int i = 0; i < Fi; i++) {
                float xv = xin[n * Fi + i];
                float4 w = W4[i * FC + c];
                acc.x += xv * w.x; acc.y += xv * w.y;
                acc.z += xv * w.z; acc.w += xv * w.w;
            }
            ((float4*)h)[n * FC + c] = acc;
        } else {
            float acc = 0.f;
            #pragma unroll
            for (int i = 0; i < Fi; i++) acc += xin[n * Fi + i] * Wsh[i * Fo + c];
            h[n * Fo + c] = acc;
        }
    }
    __syncthreads();

    // per-node attention dot products
    if (tid < NPG) {
        float sa = 0.f, sb2 = 0.f;
        #pragma unroll 4
        for (int f = 0; f < Fo; f++) {
            float hv = h[tid * Fo + f];
            sa += hv * sas[f];
            sb2 += hv * sad[f];
        }
        ss[tid] = sa;
        sd[tid] = sb2;
    }
    __syncthreads();

    // fused max/softmax/aggregate per (dst, feature-chunk), atomic-free
    for (int u = tid; u < NPG * FC; u += 256) {
        int dst = u / FC, c = u % FC;
        float sdst = ss[dst], dd = sd[dst];
        int e0 = start[dst], e1 = start[dst + 1];
        float msv = sdst;                      // self-loop seed (lrelu monotone)
        for (int j = e0; j < e1; j++) msv = fmaxf(msv, ss[elist[j]]);
        float m = lrelu(msv + dd);
        float wself = expf(lrelu(sdst + dd) - m);
        float den = wself;
        if constexpr (VEC == 4) {
            const float4* h4 = (const float4*)h;
            float4 hv = h4[dst * FC + c];
            float4 acc = {wself * hv.x, wself * hv.y, wself * hv.z, wself * hv.w};
            for (int j = e0; j < e1; j++) {
                int sc = elist[j];
                float w = expf(lrelu(ss[sc] + dd) - m);
                den += w;
                float4 hs = h4[sc * FC + c];
                acc.x += w * hs.x; acc.y += w * hs.y;
                acc.z += w * hs.z; acc.w += w * hs.w;
            }
            float inv = 1.f / (den + 1e-16f);
            int fb = c * 4;
            float o0 = fmaxf(acc.x * inv + sbi[fb + 0], 0.f);
            float o1 = fmaxf(acc.y * inv + sbi[fb + 1], 0.f);
            float o2 = fmaxf(acc.z * inv + sbi[fb + 2], 0.f);
            float o3 = fmaxf(acc.w * inv + sbi[fb + 3], 0.f);
            float4 o = {o0, o1, o2, o3};
            ((float4*)xin)[dst * FC + c] = o;
            int base = res_off + dst * Fo + fb;
            store_hl(fhi, flo, base + 0, o0);
            store_hl(fhi, flo, base + 1, o1);
            store_hl(fhi, flo, base + 2, o2);
            store_hl(fhi, flo, base + 3, o3);
        } else {
            float hv = h[dst * Fo + c];
            float acc = wself * hv;
            for (int j = e0; j < e1; j++) {
                int sc = elist[j];
                float w = expf(lrelu(ss[sc] + dd) - m);
                den += w;
                acc += w * h[sc * Fo + c];
            }
            float o = fmaxf(acc / (den + 1e-16f) + sbi[c], 0.f);
            xin[dst * Fo + c] = o;
            store_hl(fhi, flo, res_off + dst * Fo + c, o);
        }
    }
    __syncthreads();

    // pool: per-feature max over nodes
    for (int f = tid; f < Fo; f += 256) {
        float mx = -3.4e38f;
        #pragma unroll 1
        for (int n = 0; n < NPG; n++) mx = fmaxf(mx, xin[n * Fo + f]);
        store_hl(fhi, flo, pool_off + f, mx);
    }
    __syncthreads();
}

__global__ void __launch_bounds__(256)
gat_kernel(const float* __restrict__ x, const int* __restrict__ ei,
           const float* __restrict__ W1, const float* __restrict__ as1,
           const float* __restrict__ ad1, const float* __restrict__ b1,
           const float* __restrict__ W2, const float* __restrict__ as2,
           const float* __restrict__ ad2, const float* __restrict__ b2,
           const float* __restrict__ W3, const float* __restrict__ as3,
           const float* __restrict__ ad3, const float* __restrict__ b3,
           const float* __restrict__ W4, const float* __restrict__ as4,
           const float* __restrict__ ad4, const float* __restrict__ b4,
           __nv_bfloat16* __restrict__ Ahi, __nv_bfloat16* __restrict__ Alo)
{
    __shared__ __align__(16) float s_x[NPG * 64];
    __shared__ __align__(16) float s_h[NPG * 64];
    __shared__ __align__(16) float s_W[64 * 32];
    __shared__ float s_as[64], s_ad[64], s_b[64];
    __shared__ float s_s[NPG], s_d[NPG];
    __shared__ int s_start[NPG + 1];
    __shared__ int s_pos[NPG];
    __shared__ short s_elist[EPG];
    __shared__ __align__(16) __nv_bfloat16 s_fhi[KP];
    __shared__ __align__(16) __nv_bfloat16 s_flo[KP];

    const int g = blockIdx.x;
    const int tid = threadIdx.x;
    const int ebase = g * EPG;
    const int nbase = g * NPG;

    // ---- CSR build (counting sort by dst) ----
    if (tid < NPG) s_pos[tid] = 0;
    __syncthreads();
    for (int e = tid; e < EPG; e += 256) {
        int dst = ei[ETOT + ebase + e] - nbase;
        atomicAdd(&s_pos[dst], 1);
    }
    __syncthreads();
    if (tid == 0) {
        int acc = 0;
        for (int n = 0; n < NPG; n++) { s_start[n] = acc; acc += s_pos[n]; }
        s_start[NPG] = acc;
    }
    __syncthreads();
    if (tid < NPG) s_pos[tid] = s_start[tid];
    __syncthreads();
    for (int e = tid; e < EPG; e += 256) {
        int src = ei[ebase + e] - nbase;
        int dst = ei[ETOT + ebase + e] - nbase;
        int slot = atomicAdd(&s_pos[dst], 1);
        s_elist[slot] = (short)src;
    }

    // ---- init features ----
    if (tid < KP - FDIM) {
        s_fhi[FDIM + tid] = __float2bfloat16(0.f);
        s_flo[FDIM + tid] = __float2bfloat16(0.f);
    }
    if (tid < NPG) {
        float xv = x[nbase + tid];
        s_x[tid] = xv;
        store_hl(s_fhi, s_flo, OFF_RES0 + tid, xv);
    }
    __syncthreads();
    if (tid == 0) {
        float mx = -3.4e38f;
        for (int n = 0; n < NPG; n++) mx = fmaxf(mx, s_x[n]);
        store_hl(s_fhi, s_flo, OFF_OUT0, mx);
    }

    gat_layer_csr<1, 8, 4>(s_x, s_h, s_W, s_as, s_ad, s_b, s_s, s_d, s_start,
                           s_elist, W1, as1, ad1, b1, s_fhi, s_flo, OFF_RES1, OFF_OUT1);
    gat_layer_csr<8, 64, 4>(s_x, s_h, s_W, s_as, s_ad, s_b, s_s, s_d, s_start,
                            s_elist, W2, as2, ad2, b2, s_fhi, s_flo, OFF_RES2, OFF_OUT2);
    gat_layer_csr<64, 32, 4>(s_x, s_h, s_W, s_as, s_ad, s_b, s_s, s_d, s_start,
                             s_elist, W3, as3, ad3, b3, s_fhi, s_flo, OFF_RES3, OFF_OUT3);
    gat_layer_csr<32, 9, 1>(s_x, s_h, s_W, s_as, s_ad, s_b, s_s, s_d, s_start,
                            s_elist, W4, as4, ad4, b4, s_fhi, s_flo, OFF_RES4, OFF_OUT4);

    // ---- coalesced dump of the bf16 hi/lo feature row ----
    {
        const uint4* fh4 = (const uint4*)s_fhi;
        const uint4* fl4 = (const uint4*)s_flo;
        uint4* dh = (uint4*)(Ahi + (size_t)g * KP);
        uint4* dl = (uint4*)(Alo + (size_t)g * KP);
        #pragma unroll 2
        for (int i = tid; i < KP * 2 / 16; i += 256) {
            dh[i] = fh4[i];
            dl[i] = fl4[i];
        }
    }
}

// ---------------- lw1 transpose + bf16 split: [4560,1024] -> [1024,4608] ---
__global__ void __launch_bounds__(256)
convB_kernel(const float* __restrict__ lw1,
             __nv_bfloat16* __restrict__ Bhi, __nv_bfloat16* __restrict__ Blo)
{
    __shared__ float t[32][33];
    const int k0 = blockIdx.x * 32;
    const int n0 = blockIdx.y * 32;
    const int tx = threadIdx.x & 31;
    const int ty = threadIdx.x >> 5;  // 0..7
    #pragma unroll
    for (int j = 0; j < 4; j++) {
        int k = k0 + ty + j * 8;
        t[ty + j * 8][tx] = (k < FDIM) ? lw1[(size_t)k * 1024 + (n0 + tx)] : 0.f;
    }
    __syncthreads();
    #pragma unroll
    for (int j = 0; j < 4; j++) {
        int n = n0 + ty + j * 8;
        int k = k0 + tx;
        float v = t[tx][ty + j * 8];
        __nv_bfloat16 h = __float2bfloat16(v);
        Bhi[(size_t)n * KP + k] = h;
        Blo[(size_t)n * KP + k] = __float2bfloat16(v - __bfloat162float(h));
    }
}

// ---------------- GEMM1: mma.sync bf16x3, M=8192, N=1024, K=4608 -----------
#define G1_BK      32
#define G1_PITCH   80
#define G1_ARR     (128 * G1_PITCH)          // 10240 B per array
#define G1_STAGE   (4 * G1_ARR)              // 40960 B
#define G1_STAGES  3
#define G1_SMEM    (G1_STAGES * G1_STAGE)    // 122880 B
#define G1_CHUNKS  (KP / G1_BK)              // 144

__device__ __forceinline__ void g1_load(
    uint32_t st, int k0, int row0, int col0, int tid,
    const __nv_bfloat16* __restrict__ Ahi, const __nv_bfloat16* __restrict__ Alo,
    const __nv_bfloat16* __restrict__ Bhi, const __nv_bfloat16* __restrict__ Blo)
{
    #pragma unroll
    for (int j = 0; j < 2; j++) {
        int s = tid + j * 256;               // 0..511
        int row = s >> 2, ch = s & 3;
        uint32_t dst = st + (uint32_t)(row * G1_PITCH + ch * 16);
        size_t goffA = (size_t)(row0 + row) * KP + k0 + ch * 8;
        size_t goffB = (size_t)(col0 + row) * KP + k0 + ch * 8;
        cp_async16(dst,               Ahi + goffA);
        cp_async16(dst + G1_ARR,      Alo + goffA);
        cp_async16(dst + 2 * G1_ARR,  Bhi + goffB);
        cp_async16(dst + 3 * G1_ARR,  Blo + goffB);
    }
}

__global__ void __launch_bounds__(256)
gemm1_mma(const __nv_bfloat16* __restrict__ Ahi, const __nv_bfloat16* __restrict__ Alo,
          const __nv_bfloat16* __restrict__ Bhi, const __nv_bfloat16* __restrict__ Blo,
          const float* __restrict__ bias, float* __restrict__ C)
{
    extern __shared__ char dsm_raw[];
    const uint32_t dsm = smem_u32(dsm_raw);

    const int tid = threadIdx.x;
    const int wid = tid >> 5, lid = tid & 31;
    const int wm = wid & 1;
    const int wn = wid >> 1;
    const int row0 = blockIdx.y * 128;
    const int col0 = blockIdx.x * 128;

    float acc[4][4][4];
    #pragma unroll
    for (int i = 0; i < 4; i++)
        #pragma unroll
        for (int j = 0; j < 4; j++)
            #pragma unroll
            for (int k = 0; k < 4; k++) acc[i][j][k] = 0.f;

    #pragma unroll
    for (int s = 0; s < G1_STAGES - 1; s++) {
        g1_load(dsm + s * G1_STAGE, s * G1_BK, row0, col0, tid, Ahi, Alo, Bhi, Blo);
        cp_commit();
    }

    const int lr = lid & 7, g = lid >> 3;
    const uint32_t aoff = (uint32_t)((wm * 64 + lr + ((g & 1) << 3)) * G1_PITCH
                                     + ((g >> 1) << 4));
    const uint32_t boff = (uint32_t)((wn * 32 + lr + (((g >> 1) & 1) << 3)) * G1_PITCH
                                     + ((g & 1) << 4));

    for (int i = 0; i < G1_CHUNKS; i++) {
        cp_wait_group<G1_STAGES - 2>();
        __syncthreads();

        int c = i + G1_STAGES - 1;
        if (c < G1_CHUNKS)
            g1_load(dsm + (c % G1_STAGES) * G1_STAGE, c * G1_BK, row0, col0, tid,
                    Ahi, Alo, Bhi, Blo);
        cp_commit();

        const uint32_t sA  = dsm + (i % G1_STAGES) * G1_STAGE;
        const uint32_t sAl = sA + G1_ARR;
        const uint32_t sB  = sA + 2 * G1_ARR;
        const uint32_t sBl = sA + 3 * G1_ARR;

        #pragma unroll
        for (int ks = 0; ks < 2; ks++) {
            uint32_t ah[4][4], al[4][4], bh[2][4], bl[2][4];
            #pragma unroll
            for (int mf = 0; mf < 4; mf++) {
                ldsm_x4(ah[mf], sA  + aoff + mf * (16 * G1_PITCH) + ks * 32);
                ldsm_x4(al[mf], sAl + aoff + mf * (16 * G1_PITCH) + ks * 32);
            }
            #pragma unroll
            for (int nf2 = 0; nf2 < 2; nf2++) {
                ldsm_x4(bh[nf2], sB  + boff + nf2 * (16 * G1_PITCH) + ks * 32);
                ldsm_x4(bl[nf2], sBl + boff + nf2 * (16 * G1_PITCH) + ks * 32);
            }
            #pragma unroll
            for (int mf = 0; mf < 4; mf++) {
                #pragma unroll
                for (int nf = 0; nf < 4; nf++) {
                    const uint32_t* fh = &bh[nf >> 1][(nf & 1) * 2];
                    const uint32_t* fl = &bl[nf >> 1][(nf & 1) * 2];
                    mma16816(acc[mf][nf], ah[mf], fh);
                    mma16816(acc[mf][nf], ah[mf], fl);
                    mma16816(acc[mf][nf], al[mf], fh);
                }
            }
        }
    }

    const int mbase = row0 + wm * 64 + (lid >> 2);
    const int nbase = col0 + wn * 32 + (lid & 3) * 2;
    #pragma unroll
    for (int mf = 0; mf < 4; mf++) {
        #pragma unroll
        for (int nf = 0; nf < 4; nf++) {
            int r0 = mbase + mf * 16;
            int cc = nbase + nf * 8;
            float b0 = bias[cc], b1 = bias[cc + 1];
            float v0 = fmaxf(acc[mf][nf][0] + b0, 0.f);
            float v1 = fmaxf(acc[mf][nf][1] + b1, 0.f);
            float v2 = fmaxf(acc[mf][nf][2] + b0, 0.f);
            float v3 = fmaxf(acc[mf][nf][3] + b1, 0.f);
            C[(size_t)r0 * 1024 + cc]       = v0;
            C[(size_t)r0 * 1024 + cc + 1]   = v1;
            C[(size_t)(r0 + 8) * 1024 + cc]     = v2;
            C[(size_t)(r0 + 8) * 1024 + cc + 1] = v3;
        }
    }
}

// ---------------- GEMM2: pipelined fp32, [8192,1024]@[1024,128]+b, relu ----
#define G2_BK      32
#define G2_APITCH  36
#define G2_AFLOATS (32 * G2_APITCH)            // 1152 floats
#define G2_BFLOATS (G2_BK * 128)               // 4096 floats
#define G2_STGF    (G2_AFLOATS + G2_BFLOATS)   // 5248 floats = 20992 B
#define G2_STAGES  3
#define G2_SMEM    (G2_STAGES * G2_STGF * 4)   // 62976 B
#define G2_CHUNKS  (1024 / G2_BK)              // 32

__device__ __forceinline__ void g2_load(
    uint32_t st, const float* __restrict__ A, const float* __restrict__ B,
    int row0, int k0, int tid)
{
    int row = tid >> 3, kc = tid & 7;
    cp_async16(st + (uint32_t)(row * G2_APITCH + kc * 4) * 4,
               A + (size_t)(row0 + row) * 1024 + k0 + kc * 4);
    #pragma unroll
    for (int j = 0; j < 4; j++) {
        int idx = tid + j * 256;
        int kk = idx >> 5, c4 = idx & 31;
        cp_async16(st + (uint32_t)(G2_AFLOATS + kk * 128 + c4 * 4) * 4,
                   B + (size_t)(k0 + kk) * 128 + c4 * 4);
    }
}

__global__ void __launch_bounds__(256)
gemm2_mlp(const float* __restrict__ A, const float* __restrict__ Bm,
          const float* __restrict__ bias, float* __restrict__ C)
{
    extern __shared__ char dsm_raw[];
    float* dsm_f = (float*)dsm_raw;
    const uint32_t dsm = smem_u32(dsm_raw);

    const int tid = threadIdx.x;
    const int tr = tid >> 5;       // 0..7 -> rows tr*4..+3
    const int tc = tid & 31;       // cols tc*4..+3
    const int row0 = blockIdx.x * 32;

    unsigned long long acc[4][2];
    #pragma unroll
    for (int i = 0; i < 4; i++) { acc[i][0] = 0ull; acc[i][1] = 0ull; }

    #pragma unroll
    for (int s = 0; s < G2_STAGES - 1; s++) {
        g2_load(dsm + s * (G2_STGF * 4), A, Bm, row0, s * G2_BK, tid);
        cp_commit();
    }

    for (int i = 0; i < G2_CHUNKS; i++) {
        cp_wait_group<G2_STAGES - 2>();
        __syncthreads();

        int c = i + G2_STAGES - 1;
        if (c < G2_CHUNKS)
            g2_load(dsm + (c % G2_STAGES) * (G2_STGF * 4), A, Bm, row0,
                    c * G2_BK, tid);
        cp_commit();

        const float* As = dsm_f + (i % G2_STAGES) * G2_STGF;
        const float* Bs = As + G2_AFLOATS;

        #pragma unroll
        for (int kk = 0; kk < G2_BK; kk++) {
            float a0 = As[(tr * 4 + 0) * G2_APITCH + kk];
            float a1 = As[(tr * 4 + 1) * G2_APITCH + kk];
            float a2 = As[(tr * 4 + 2) * G2_APITCH + kk];
            float a3 = As[(tr * 4 + 3) * G2_APITCH + kk];
            float4 bv = *(const float4*)&Bs[kk * 128 + tc * 4];
            unsigned long long bp0 = pk2(bv.x, bv.y);
            unsigned long long bp1 = pk2(bv.z, bv.w);
            unsigned long long ai;
            ai = pk2(a0, a0); ffma2(acc[0][0], ai, bp0); ffma2(acc[0][1], ai, bp1);
            ai = pk2(a1, a1); ffma2(acc[1][0], ai, bp0); ffma2(acc[1][1], ai, bp1);
            ai = pk2(a2, a2); ffma2(acc[2][0], ai, bp0); ffma2(acc[2][1], ai, bp1);
            ai = pk2(a3, a3); ffma2(acc[3][0], ai, bp0); ffma2(acc[3][1], ai, bp1);
        }
    }

    float4 bvec = *(const float4*)&bias[tc * 4];
    #pragma unroll
    for (int i = 0; i < 4; i++) {
        float v0, v1, v2, v3;
        upk2(acc[i][0], v0, v1);
        upk2(acc[i][1], v2, v3);
        float4 o;
        o.x = fmaxf(v0 + bvec.x, 0.f);
        o.y = fmaxf(v1 + bvec.y, 0.f);
        o.z = fmaxf(v2 + bvec.z, 0.f);
        o.w = fmaxf(v3 + bvec.w, 0.f);
        *(float4*)&C[(size_t)(row0 + tr * 4 + i) * 128 + tc * 4] = o;
    }
}

// ---------------- final tiny GEMM ----------------
__global__ void gemm3_kernel(const float* __restrict__ A, const float* __restrict__ W,
                             const float* __restrict__ bias, float* __restrict__ C)
{
    int idx = blockIdx.x * blockDim.x + threadIdx.x;
    if (idx >= NGRAPH * 9) return;
    int m = idx / 9, n = idx - m * 9;
    const float* a = A + (size_t)m * 128;
    float acc = 0.f;
    #pragma unroll 8
    for (int k = 0; k < 128; k++) acc += a[k] * W[k * 9 + n];
    C[idx] = acc + bias[n];
}

// ---------------- launch ----------------
extern "C" void kernel_launch(void* const* d_in, const int* in_sizes, int n_in,
                              void* d_out, int out_size)
{
    (void)in_sizes; (void)n_in; (void)out_size;
    const float* x   = (const float*)d_in[0];
    const int*   ei  = (const int*)d_in[1];
    const float* W1  = (const float*)d_in[3];
    const float* as1 = (const float*)d_in[4];
    const float* ad1 = (const float*)d_in[5];
    const float* b1  = (const float*)d_in[6];
    const float* W2  = (const float*)d_in[7];
    const float* as2 = (const float*)d_in[8];
    const float* ad2 = (const float*)d_in[9];
    const float* b2  = (const float*)d_in[10];
    const float* W3  = (const float*)d_in[11];
    const float* as3 = (const float*)d_in[12];
    const float* ad3 = (const float*)d_in[13];
    const float* b3  = (const float*)d_in[14];
    const float* W4  = (const float*)d_in[15];
    const float* as4 = (const float*)d_in[16];
    const float* ad4 = (const float*)d_in[17];
    const float* b4  = (const float*)d_in[18];
    const float* lw1 = (const float*)d_in[19];
    const float* lb1 = (const float*)d_in[20];
    const float* lw2 = (const float*)d_in[21];
    const float* lb2 = (const float*)d_in[22];
    const float* lw3 = (const float*)d_in[23];
    const float* lb3 = (const float*)d_in[24];
    float* out = (float*)d_out;

    __nv_bfloat16 *Ahi, *Alo, *Bhi, *Blo;
    float *m1, *m2;
    cudaGetSymbolAddress((void**)&Ahi, g_Ahi);
    cudaGetSymbolAddress((void**)&Alo, g_Alo);
    cudaGetSymbolAddress((void**)&Bhi, g_Bhi);
    cudaGetSymbolAddress((void**)&Blo, g_Blo);
    cudaGetSymbolAddress((void**)&m1, g_m1);
    cudaGetSymbolAddress((void**)&m2, g_m2);

    cudaFuncSetAttribute(gemm1_mma, cudaFuncAttributeMaxDynamicSharedMemorySize,
                         G1_SMEM);
    cudaFuncSetAttribute(gemm2_mlp, cudaFuncAttributeMaxDynamicSharedMemorySize,
                         G2_SMEM);

    convB_kernel<<<dim3(KP / 32, 1024 / 32), 256>>>(lw1, Bhi, Blo);
    gat_kernel<<<NGRAPH, 256>>>(x, ei, W1, as1, ad1, b1, W2, as2, ad2, b2,
                                W3, as3, ad3, b3, W4, as4, ad4, b4, Ahi, Alo);

    gemm1_mma<<<dim3(1024 / 128, NGRAPH / 128), 256, G1_SMEM>>>(
        Ahi, Alo, Bhi, Blo, lb1, m1);

    gemm2_mlp<<<NGRAPH / 32, 256, G2_SMEM>>>(m1, lw2, lb2, m2);
    gemm3_kernel<<<(NGRAPH * 9 + 255) / 256, 256>>>(m2, lw3, lb3, out);
}

// round 14
// speedup vs baseline: 1.3698x; 1.3698x over previous
#include <cuda_runtime.h>
#include <cuda_bf16.h>
#include <cuda_fp16.h>
#include <cstdint>

// ---------------- problem constants ----------------
#define NGRAPH 8192
#define NPG    39
#define EPG    312
#define NTOT   (NGRAPH * NPG)
#define ETOT   (NGRAPH * EPG)
#define FDIM   4560
#define KP     4608            // FDIM padded to 64
#define NEG_SLOPE 0.2f

#define OFF_RES0 0
#define OFF_RES1 39
#define OFF_RES2 351
#define OFF_RES3 2847
#define OFF_RES4 4095
#define OFF_OUT0 4446
#define OFF_OUT1 4447
#define OFF_OUT2 4455
#define OFF_OUT3 4519
#define OFF_OUT4 4551

// ---------------- scratch (device globals) ----------------
__device__ __half g_Af[(size_t)NGRAPH * KP];    // 75.5 MB (fp16 features)
__device__ __half g_Bf[(size_t)1024 * KP];      // 9.4 MB (fp16 lw1^T)
__device__ float g_m1[(size_t)NGRAPH * 1024];   // 33.5 MB
__device__ float g_m2[(size_t)NGRAPH * 128];    // 4.2 MB

// ---------------- generic helpers ----------------
__device__ __forceinline__ float lrelu(float v) { return v >= 0.f ? v : NEG_SLOPE * v; }
__device__ __forceinline__ uint32_t smem_u32(const void* p) {
    uint32_t a;
    asm("{ .reg .u64 t; cvta.to.shared.u64 t, %1; cvt.u32.u64 %0, t; }" : "=r"(a) : "l"(p));
    return a;
}

// f32x2 packed FMA helpers
__device__ __forceinline__ unsigned long long pk2(float x, float y) {
    unsigned long long u;
    asm("mov.b64 %0, {%1, %2};" : "=l"(u) : "f"(x), "f"(y));
    return u;
}
__device__ __forceinline__ void upk2(unsigned long long u, float& x, float& y) {
    asm("mov.b64 {%0, %1}, %2;" : "=f"(x), "=f"(y) : "l"(u));
}
__device__ __forceinline__ void ffma2(unsigned long long& c, unsigned long long a,
                                      unsigned long long b) {
    asm("fma.rn.f32x2 %0, %1, %2, %0;" : "+l"(c) : "l"(a), "l"(b));
}

// ---------------- cp.async / ldmatrix / mma helpers ----------------
__device__ __forceinline__ void cp_async16(uint32_t dst, const void* src) {
    asm volatile("cp.async.cg.shared.global [%0], [%1], 16;" :: "r"(dst), "l"(src));
}
__device__ __forceinline__ void cp_commit() {
    asm volatile("cp.async.commit_group;" ::: "memory");
}
template <int N>
__device__ __forceinline__ void cp_wait_group() {
    asm volatile("cp.async.wait_group %0;" :: "n"(N) : "memory");
}
__device__ __forceinline__ void ldsm_x4(uint32_t* r, uint32_t addr) {
    asm volatile("ldmatrix.sync.aligned.m8n8.x4.shared.b16 {%0,%1,%2,%3}, [%4];"
                 : "=r"(r[0]), "=r"(r[1]), "=r"(r[2]), "=r"(r[3]) : "r"(addr));
}
// fp16 x fp16 -> fp32 MMA
__device__ __forceinline__ void mma16816h(float* c, const uint32_t* a, const uint32_t* b) {
    asm volatile(
        "mma.sync.aligned.m16n8k16.row.col.f32.f16.f16.f32 "
        "{%0,%1,%2,%3}, {%4,%5,%6,%7}, {%8,%9}, {%0,%1,%2,%3};"
        : "+f"(c[0]), "+f"(c[1]), "+f"(c[2]), "+f"(c[3])
        : "r"(a[0]), "r"(a[1]), "r"(a[2]), "r"(a[3]), "r"(b[0]), "r"(b[1]));
}

// ================= GAT kernel: one CTA per graph, CSR aggregation ==========
template <int Fi, int Fo, int VEC>
__device__ void gat_layer_csr(
    float* __restrict__ xin, float* __restrict__ h, float* __restrict__ Wsh,
    float* __restrict__ sas, float* __restrict__ sad, float* __restrict__ sbi,
    float* __restrict__ ss, float* __restrict__ sd,
    const int* __restrict__ start, const short* __restrict__ elist,
    const float* __restrict__ W, const float* __restrict__ a_s,
    const float* __restrict__ a_d, const float* __restrict__ bias,
    __half* __restrict__ fh, int res_off, int pool_off)
{
    const int tid = threadIdx.x;
    for (int i = tid; i < Fi * Fo; i += 256) Wsh[i] = W[i];
    if (tid < Fo) { sas[tid] = a_s[tid]; sad[tid] = a_d[tid]; sbi[tid] = bias[tid]; }
    __syncthreads();

    constexpr int FC = Fo / VEC;
    // h = x @ W (vectorized over output features)
    for (int u = tid; u < NPG * FC; u += 256) {
        int n = u / FC, c = u % FC;
        if constexpr (VEC == 4) {
            const float4* W4 = (const float4*)Wsh;
            float4 acc = {0.f, 0.f, 0.f, 0.f};
            #pragma unroll
            for (int i = 0; i < Fi; i++) {
                float xv = xin[n * Fi + i];
                float4 w = W4[i * FC + c];
                acc.x += xv * w.x; acc.y += xv * w.y;
                acc.z += xv * w.z; acc.w += xv * w.w;
            }
            ((float4*)h)[n * FC + c] = acc;
        } else {
            float acc = 0.f;
            #pragma unroll
            for (int i = 0; i < Fi; i++) acc += xin[n * Fi + i] * Wsh[i * Fo + c];
            h[n * Fo + c] = acc;
        }
    }
    __syncthreads();

    // per-node attention dot products
    if (tid < NPG) {
        float sa = 0.f, sb2 = 0.f;
        #pragma unroll 4
        for (int f = 0; f < Fo; f++) {
            float hv = h[tid * Fo + f];
            sa += hv * sas[f];
            sb2 += hv * sad[f];
        }
        ss[tid] = sa;
        sd[tid] = sb2;
    }
    __syncthreads();

    // fused max/softmax/aggregate per (dst, feature-chunk), atomic-free
    for (int u = tid; u < NPG * FC; u += 256) {
        int dst = u / FC, c = u % FC;
        float sdst = ss[dst], dd = sd[dst];
        int e0 = start[dst], e1 = start[dst + 1];
        float msv = sdst;                      // self-loop seed (lrelu monotone)
        for (int j = e0; j < e1; j++) msv = fmaxf(msv, ss[elist[j]]);
        float m = lrelu(msv + dd);
        float wself = expf(lrelu(sdst + dd) - m);
        float den = wself;
        if constexpr (VEC == 4) {
            const float4* h4 = (const float4*)h;
            float4 hv = h4[dst * FC + c];
            float4 acc = {wself * hv.x, wself * hv.y, wself * hv.z, wself * hv.w};
            for (int j = e0; j < e1; j++) {
                int sc = elist[j];
                float w = expf(lrelu(ss[sc] + dd) - m);
                den += w;
                float4 hs = h4[sc * FC + c];
                acc.x += w * hs.x; acc.y += w * hs.y;
                acc.z += w * hs.z; acc.w += w * hs.w;
            }
            float inv = 1.f / (den + 1e-16f);
            int fb = c * 4;
            float o0 = fmaxf(acc.x * inv + sbi[fb + 0], 0.f);
            float o1 = fmaxf(acc.y * inv + sbi[fb + 1], 0.f);
            float o2 = fmaxf(acc.z * inv + sbi[fb + 2], 0.f);
            float o3 = fmaxf(acc.w * inv + sbi[fb + 3], 0.f);
            float4 o = {o0, o1, o2, o3};
            ((float4*)xin)[dst * FC + c] = o;
            int base = res_off + dst * Fo + fb;
            fh[base + 0] = __float2half(o0);
            fh[base + 1] = __float2half(o1);
            fh[base + 2] = __float2half(o2);
            fh[base + 3] = __float2half(o3);
        } else {
            float hv = h[dst * Fo + c];
            float acc = wself * hv;
            for (int j = e0; j < e1; j++) {
                int sc = elist[j];
                float w = expf(lrelu(ss[sc] + dd) - m);
                den += w;
                acc += w * h[sc * Fo + c];
            }
            float o = fmaxf(acc / (den + 1e-16f) + sbi[c], 0.f);
            xin[dst * Fo + c] = o;
            fh[res_off + dst * Fo + c] = __float2half(o);
        }
    }
    __syncthreads();

    // pool: per-feature max over nodes
    for (int f = tid; f < Fo; f += 256) {
        float mx = -3.4e38f;
        #pragma unroll 1
        for (int n = 0; n < NPG; n++) mx = fmaxf(mx, xin[n * Fo + f]);
        fh[pool_off + f] = __float2half(mx);
    }
    __syncthreads();
}

__global__ void __launch_bounds__(256)
gat_kernel(const float* __restrict__ x, const int* __restrict__ ei,
           const float* __restrict__ W1, const float* __restrict__ as1,
           const float* __restrict__ ad1, const float* __restrict__ b1,
           const float* __restrict__ W2, const float* __restrict__ as2,
           const float* __restrict__ ad2, const float* __restrict__ b2,
           const float* __restrict__ W3, const float* __restrict__ as3,
           const float* __restrict__ ad3, const float* __restrict__ b3,
           const float* __restrict__ W4, const float* __restrict__ as4,
           const float* __restrict__ ad4, const float* __restrict__ b4,
           __half* __restrict__ Af)
{
    __shared__ __align__(16) float s_x[NPG * 64];
    __shared__ __align__(16) float s_h[NPG * 64];
    __shared__ __align__(16) float s_W[64 * 32];
    __shared__ float s_as[64], s_ad[64], s_b[64];
    __shared__ float s_s[NPG], s_d[NPG];
    __shared__ int s_start[NPG + 1];
    __shared__ int s_pos[NPG];
    __shared__ short s_elist[EPG];
    __shared__ __align__(16) __half s_fh[KP];

    const int g = blockIdx.x;
    const int tid = threadIdx.x;
    const int ebase = g * EPG;
    const int nbase = g * NPG;

    // ---- CSR build (counting sort by dst) ----
    if (tid < NPG) s_pos[tid] = 0;
    __syncthreads();
    for (int e = tid; e < EPG; e += 256) {
        int dst = ei[ETOT + ebase + e] - nbase;
        atomicAdd(&s_pos[dst], 1);
    }
    __syncthreads();
    if (tid == 0) {
        int acc = 0;
        for (int n = 0; n < NPG; n++) { s_start[n] = acc; acc += s_pos[n]; }
        s_start[NPG] = acc;
    }
    __syncthreads();
    if (tid < NPG) s_pos[tid] = s_start[tid];
    __syncthreads();
    for (int e = tid; e < EPG; e += 256) {
        int src = ei[ebase + e] - nbase;
        int dst = ei[ETOT + ebase + e] - nbase;
        int slot = atomicAdd(&s_pos[dst], 1);
        s_elist[slot] = (short)src;
    }

    // ---- init features ----
    if (tid < KP - FDIM) s_fh[FDIM + tid] = __float2half(0.f);
    if (tid < NPG) {
        float xv = x[nbase + tid];
        s_x[tid] = xv;
        s_fh[OFF_RES0 + tid] = __float2half(xv);
    }
    __syncthreads();
    if (tid == 0) {
        float mx = -3.4e38f;
        for (int n = 0; n < NPG; n++) mx = fmaxf(mx, s_x[n]);
        s_fh[OFF_OUT0] = __float2half(mx);
    }

    gat_layer_csr<1, 8, 4>(s_x, s_h, s_W, s_as, s_ad, s_b, s_s, s_d, s_start,
                           s_elist, W1, as1, ad1, b1, s_fh, OFF_RES1, OFF_OUT1);
    gat_layer_csr<8, 64, 4>(s_x, s_h, s_W, s_as, s_ad, s_b, s_s, s_d, s_start,
                            s_elist, W2, as2, ad2, b2, s_fh, OFF_RES2, OFF_OUT2);
    gat_layer_csr<64, 32, 4>(s_x, s_h, s_W, s_as, s_ad, s_b, s_s, s_d, s_start,
                             s_elist, W3, as3, ad3, b3, s_fh, OFF_RES3, OFF_OUT3);
    gat_layer_csr<32, 9, 1>(s_x, s_h, s_W, s_as, s_ad, s_b, s_s, s_d, s_start,
                            s_elist, W4, as4, ad4, b4, s_fh, OFF_RES4, OFF_OUT4);

    // ---- coalesced dump of the fp16 feature row ----
    {
        const uint4* f4 = (const uint4*)s_fh;
        uint4* d4 = (uint4*)(Af + (size_t)g * KP);
        #pragma unroll 2
        for (int i = tid; i < KP * 2 / 16; i += 256) d4[i] = f4[i];
    }
}

// ---------------- lw1 transpose to fp16: [4560,1024] -> [1024,4608] -------
__global__ void __launch_bounds__(256)
convB_kernel(const float* __restrict__ lw1, __half* __restrict__ Bf)
{
    __shared__ float t[32][33];
    const int k0 = blockIdx.x * 32;
    const int n0 = blockIdx.y * 32;
    const int tx = threadIdx.x & 31;
    const int ty = threadIdx.x >> 5;  // 0..7
    #pragma unroll
    for (int j = 0; j < 4; j++) {
        int k = k0 + ty + j * 8;
        t[ty + j * 8][tx] = (k < FDIM) ? lw1[(size_t)k * 1024 + (n0 + tx)] : 0.f;
    }
    __syncthreads();
    #pragma unroll
    for (int j = 0; j < 4; j++) {
        int n = n0 + ty + j * 8;
        int k = k0 + tx;
        Bf[(size_t)n * KP + k] = __float2half(t[tx][ty + j * 8]);
    }
}

// ---------------- GEMM1: mma.sync fp16x1, M=8192, N=1024, K=4608 -----------
// Tiles: BM=128, BN=128, BK=32, 3-stage cp.async pipeline.
// smem rows: 32 fp16 = 64B data at 80B pitch -> conflict-free ldmatrix.
#define G1_BK      32
#define G1_PITCH   80
#define G1_ARR     (128 * G1_PITCH)          // 10240 B per array
#define G1_STAGE   (2 * G1_ARR)              // 20480 B (A | B)
#define G1_STAGES  3
#define G1_SMEM    (G1_STAGES * G1_STAGE)    // 61440 B
#define G1_CHUNKS  (KP / G1_BK)              // 144

__device__ __forceinline__ void g1_load(
    uint32_t st, int k0, int row0, int col0, int tid,
    const __half* __restrict__ Af, const __half* __restrict__ Bf)
{
    #pragma unroll
    for (int j = 0; j < 2; j++) {
        int s = tid + j * 256;               // 0..511
        int row = s >> 2, ch = s & 3;
        uint32_t dst = st + (uint32_t)(row * G1_PITCH + ch * 16);
        cp_async16(dst,          Af + (size_t)(row0 + row) * KP + k0 + ch * 8);
        cp_async16(dst + G1_ARR, Bf + (size_t)(col0 + row) * KP + k0 + ch * 8);
    }
}

__global__ void __launch_bounds__(256)
gemm1_mma(const __half* __restrict__ Af, const __half* __restrict__ Bf,
          const float* __restrict__ bias, float* __restrict__ C)
{
    extern __shared__ char dsm_raw[];
    const uint32_t dsm = smem_u32(dsm_raw);

    const int tid = threadIdx.x;
    const int wid = tid >> 5, lid = tid & 31;
    const int wm = wid & 1;          // 2 warps along M (64 each)
    const int wn = wid >> 1;         // 4 warps along N (32 each)
    const int row0 = blockIdx.y * 128;
    const int col0 = blockIdx.x * 128;

    float acc[4][4][4];
    #pragma unroll
    for (int i = 0; i < 4; i++)
        #pragma unroll
        for (int j = 0; j < 4; j++)
            #pragma unroll
            for (int k = 0; k < 4; k++) acc[i][j][k] = 0.f;

    #pragma unroll
    for (int s = 0; s < G1_STAGES - 1; s++) {
        g1_load(dsm + s * G1_STAGE, s * G1_BK, row0, col0, tid, Af, Bf);
        cp_commit();
    }

    const int lr = lid & 7, g = lid >> 3;
    const uint32_t aoff = (uint32_t)((wm * 64 + lr + ((g & 1) << 3)) * G1_PITCH
                                     + ((g >> 1) << 4));
    const uint32_t boff = (uint32_t)((wn * 32 + lr + (((g >> 1) & 1) << 3)) * G1_PITCH
                                     + ((g & 1) << 4));

    for (int i = 0; i < G1_CHUNKS; i++) {
        cp_wait_group<G1_STAGES - 2>();
        __syncthreads();

        int c = i + G1_STAGES - 1;
        if (c < G1_CHUNKS)
            g1_load(dsm + (c % G1_STAGES) * G1_STAGE, c * G1_BK, row0, col0, tid,
                    Af, Bf);
        cp_commit();

        const uint32_t sA = dsm + (i % G1_STAGES) * G1_STAGE;
        const uint32_t sB = sA + G1_ARR;

        #pragma unroll
        for (int ks = 0; ks < 2; ks++) {
            uint32_t ah[4][4], bh[2][4];
            #pragma unroll
            for (int mf = 0; mf < 4; mf++)
                ldsm_x4(ah[mf], sA + aoff + mf * (16 * G1_PITCH) + ks * 32);
            #pragma unroll
            for (int nf2 = 0; nf2 < 2; nf2++)
                ldsm_x4(bh[nf2], sB + boff + nf2 * (16 * G1_PITCH) + ks * 32);
            #pragma unroll
            for (int mf = 0; mf < 4; mf++) {
                #pragma unroll
                for (int nf = 0; nf < 4; nf++)
                    mma16816h(acc[mf][nf], ah[mf], &bh[nf >> 1][(nf & 1) * 2]);
            }
        }
    }

    const int mbase = row0 + wm * 64 + (lid >> 2);
    const int nbase = col0 + wn * 32 + (lid & 3) * 2;
    #pragma unroll
    for (int mf = 0; mf < 4; mf++) {
        #pragma unroll
        for (int nf = 0; nf < 4; nf++) {
            int r0 = mbase + mf * 16;
            int cc = nbase + nf * 8;
            float b0 = bias[cc], b1 = bias[cc + 1];
            float v0 = fmaxf(acc[mf][nf][0] + b0, 0.f);
            float v1 = fmaxf(acc[mf][nf][1] + b1, 0.f);
            float v2 = fmaxf(acc[mf][nf][2] + b0, 0.f);
            float v3 = fmaxf(acc[mf][nf][3] + b1, 0.f);
            C[(size_t)r0 * 1024 + cc]       = v0;
            C[(size_t)r0 * 1024 + cc + 1]   = v1;
            C[(size_t)(r0 + 8) * 1024 + cc]     = v2;
            C[(size_t)(r0 + 8) * 1024 + cc + 1] = v3;
        }
    }
}

// ---------------- GEMM2: pipelined fp32, [8192,1024]@[1024,128]+b, relu ----
#define G2_BK      32
#define G2_APITCH  36
#define G2_AFLOATS (32 * G2_APITCH)            // 1152 floats
#define G2_BFLOATS (G2_BK * 128)               // 4096 floats
#define G2_STGF    (G2_AFLOATS + G2_BFLOATS)   // 5248 floats = 20992 B
#define G2_STAGES  3
#define G2_SMEM    (G2_STAGES * G2_STGF * 4)   // 62976 B
#define G2_CHUNKS  (1024 / G2_BK)              // 32

__device__ __forceinline__ void g2_load(
    uint32_t st, const float* __restrict__ A, const float* __restrict__ B,
    int row0, int k0, int tid)
{
    int row = tid >> 3, kc = tid & 7;
    cp_async16(st + (uint32_t)(row * G2_APITCH + kc * 4) * 4,
               A + (size_t)(row0 + row) * 1024 + k0 + kc * 4);
    #pragma unroll
    for (int j = 0; j < 4; j++) {
        int idx = tid + j * 256;
        int kk = idx >> 5, c4 = idx & 31;
        cp_async16(st + (uint32_t)(G2_AFLOATS + kk * 128 + c4 * 4) * 4,
                   B + (size_t)(k0 + kk) * 128 + c4 * 4);
    }
}

__global__ void __launch_bounds__(256)
gemm2_mlp(const float* __restrict__ A, const float* __restrict__ Bm,
          const float* __restrict__ bias, float* __restrict__ C)
{
    extern __shared__ char dsm_raw[];
    float* dsm_f = (float*)dsm_raw;
    const uint32_t dsm = smem_u32(dsm_raw);

    const int tid = threadIdx.x;
    const int tr = tid >> 5;       // 0..7 -> rows tr*4..+3
    const int tc = tid & 31;       // cols tc*4..+3
    const int row0 = blockIdx.x * 32;

    unsigned long long acc[4][2];
    #pragma unroll
    for (int i = 0; i < 4; i++) { acc[i][0] = 0ull; acc[i][1] = 0ull; }

    #pragma unroll
    for (int s = 0; s < G2_STAGES - 1; s++) {
        g2_load(dsm + s * (G2_STGF * 4), A, Bm, row0, s * G2_BK, tid);
        cp_commit();
    }

    for (int i = 0; i < G2_CHUNKS; i++) {
        cp_wait_group<G2_STAGES - 2>();
        __syncthreads();

        int c = i + G2_STAGES - 1;
        if (c < G2_CHUNKS)
            g2_load(dsm + (c % G2_STAGES) * (G2_STGF * 4), A, Bm, row0,
                    c * G2_BK, tid);
        cp_commit();

        const float* As = dsm_f + (i % G2_STAGES) * G2_STGF;
        const float* Bs = As + G2_AFLOATS;

        #pragma unroll
        for (int kk = 0; kk < G2_BK; kk++) {
            float a0 = As[(tr * 4 + 0) * G2_APITCH + kk];
            float a1 = As[(tr * 4 + 1) * G2_APITCH + kk];
            float a2 = As[(tr * 4 + 2) * G2_APITCH + kk];
            float a3 = As[(tr * 4 + 3) * G2_APITCH + kk];
            float4 bv = *(const float4*)&Bs[kk * 128 + tc * 4];
            unsigned long long bp0 = pk2(bv.x, bv.y);
            unsigned long long bp1 = pk2(bv.z, bv.w);
            unsigned long long ai;
            ai = pk2(a0, a0); ffma2(acc[0][0], ai, bp0); ffma2(acc[0][1], ai, bp1);
            ai = pk2(a1, a1); ffma2(acc[1][0], ai, bp0); ffma2(acc[1][1], ai, bp1);
            ai = pk2(a2, a2); ffma2(acc[2][0], ai, bp0); ffma2(acc[2][1], ai, bp1);
            ai = pk2(a3, a3); ffma2(acc[3][0], ai, bp0); ffma2(acc[3][1], ai, bp1);
        }
    }

    float4 bvec = *(const float4*)&bias[tc * 4];
    #pragma unroll
    for (int i = 0; i < 4; i++) {
        float v0, v1, v2, v3;
        upk2(acc[i][0], v0, v1);
        upk2(acc[i][1], v2, v3);
        float4 o;
        o.x = fmaxf(v0 + bvec.x, 0.f);
        o.y = fmaxf(v1 + bvec.y, 0.f);
        o.z = fmaxf(v2 + bvec.z, 0.f);
        o.w = fmaxf(v3 + bvec.w, 0.f);
        *(float4*)&C[(size_t)(row0 + tr * 4 + i) * 128 + tc * 4] = o;
    }
}

// ---------------- final tiny GEMM ----------------
__global__ void gemm3_kernel(const float* __restrict__ A, const float* __restrict__ W,
                             const float* __restrict__ bias, float* __restrict__ C)
{
    int idx = blockIdx.x * blockDim.x + threadIdx.x;
    if (idx >= NGRAPH * 9) return;
    int m = idx / 9, n = idx - m * 9;
    const float* a = A + (size_t)m * 128;
    float acc = 0.f;
    #pragma unroll 8
    for (int k = 0; k < 128; k++) acc += a[k] * W[k * 9 + n];
    C[idx] = acc + bias[n];
}

// ---------------- launch ----------------
extern "C" void kernel_launch(void* const* d_in, const int* in_sizes, int n_in,
                              void* d_out, int out_size)
{
    (void)in_sizes; (void)n_in; (void)out_size;
    const float* x   = (const float*)d_in[0];
    const int*   ei  = (const int*)d_in[1];
    const float* W1  = (const float*)d_in[3];
    const float* as1 = (const float*)d_in[4];
    const float* ad1 = (const float*)d_in[5];
    const float* b1  = (const float*)d_in[6];
    const float* W2  = (const float*)d_in[7];
    const float* as2 = (const float*)d_in[8];
    const float* ad2 = (const float*)d_in[9];
    const float* b2  = (const float*)d_in[10];
    const float* W3  = (const float*)d_in[11];
    const float* as3 = (const float*)d_in[12];
    const float* ad3 = (const float*)d_in[13];
    const float* b3  = (const float*)d_in[14];
    const float* W4  = (const float*)d_in[15];
    const float* as4 = (const float*)d_in[16];
    const float* ad4 = (const float*)d_in[17];
    const float* b4  = (const float*)d_in[18];
    const float* lw1 = (const float*)d_in[19];
    const float* lb1 = (const float*)d_in[20];
    const float* lw2 = (const float*)d_in[21];
    const float* lb2 = (const float*)d_in[22];
    const float* lw3 = (const float*)d_in[23];
    const float* lb3 = (const float*)d_in[24];
    float* out = (float*)d_out;

    __half *Af, *Bf;
    float *m1, *m2;
    cudaGetSymbolAddress((void**)&Af, g_Af);
    cudaGetSymbolAddress((void**)&Bf, g_Bf);
    cudaGetSymbolAddress((void**)&m1, g_m1);
    cudaGetSymbolAddress((void**)&m2, g_m2);

    cudaFuncSetAttribute(gemm1_mma, cudaFuncAttributeMaxDynamicSharedMemorySize,
                         G1_SMEM);
    cudaFuncSetAttribute(gemm2_mlp, cudaFuncAttributeMaxDynamicSharedMemorySize,
                         G2_SMEM);

    convB_kernel<<<dim3(KP / 32, 1024 / 32), 256>>>(lw1, Bf);
    gat_kernel<<<NGRAPH, 256>>>(x, ei, W1, as1, ad1, b1, W2, as2, ad2, b2,
                                W3, as3, ad3, b3, W4, as4, ad4, b4, Af);

    gemm1_mma<<<dim3(1024 / 128, NGRAPH / 128), 256, G1_SMEM>>>(Af, Bf, lb1, m1);

    gemm2_mlp<<<NGRAPH / 32, 256, G2_SMEM>>>(m1, lw2, lb2, m2);
    gemm3_kernel<<<(NGRAPH * 9 + 255) / 256, 256>>>(m2, lw3, lb3, out);
}